// round 1
// baseline (speedup 1.0000x reference)
#include <cuda_runtime.h>
#include <math.h>

#define NTOK 32768
#define DM   2048
#define CORE 1024
#define MSLOT 256
#define NH   8
#define HD   128
#define INTER 4096
#define TOPK 4

// ---------------- scratch (device globals; no allocation) ----------------
__device__ float g_kv[NTOK * CORE];          // 128 MB
__device__ float g_hid[MSLOT * INTER];
__device__ float g_qslots[MSLOT * CORE];
__device__ float g_att[NH * MSLOT * HD];
__device__ unsigned int g_idx[NH * NTOK];    // packed 4 x u8 slot ids
__device__ int g_counts[NH * MSLOT];
__device__ float g_updin[MSLOT * 2 * CORE];
__device__ float g_h1[MSLOT * 2 * CORE];
__device__ float g_hu[MSLOT * 2 * CORE];
__device__ float g_h2[MSLOT * CORE];

// ---------------- generic SGEMM: C = A[MxK] @ B[KxN] + bias, opt relu ----
// BM=BN=128, BK=16, 256 threads, 8x8 micro-tile. Requires M%128==0, N%128==0, K%16==0.
template <bool RELU>
__global__ __launch_bounds__(256) void sgemm_bias(
    const float* __restrict__ A, const float* __restrict__ B,
    const float* __restrict__ bias, float* __restrict__ C,
    int M, int N, int K)
{
    __shared__ float As[16][128];
    __shared__ float Bs[16][128];

    const int tid = threadIdx.x;
    const int bm = blockIdx.y * 128;
    const int bn = blockIdx.x * 128;
    const int tx = tid & 15;      // n dir
    const int ty = tid >> 4;      // m dir

    const int arow = tid >> 2;          // 0..63
    const int acol = (tid & 3) * 4;     // 0,4,8,12
    const int brow = tid >> 5;          // 0..7
    const int bcol = (tid & 31) * 4;

    float acc[8][8];
#pragma unroll
    for (int i = 0; i < 8; i++)
#pragma unroll
        for (int j = 0; j < 8; j++) acc[i][j] = 0.f;

    for (int k0 = 0; k0 < K; k0 += 16) {
        float4 a0 = *(const float4*)&A[(size_t)(bm + arow) * K + k0 + acol];
        float4 a1 = *(const float4*)&A[(size_t)(bm + arow + 64) * K + k0 + acol];
        As[acol + 0][arow] = a0.x; As[acol + 1][arow] = a0.y;
        As[acol + 2][arow] = a0.z; As[acol + 3][arow] = a0.w;
        As[acol + 0][arow + 64] = a1.x; As[acol + 1][arow + 64] = a1.y;
        As[acol + 2][arow + 64] = a1.z; As[acol + 3][arow + 64] = a1.w;
        *(float4*)&Bs[brow][bcol]     = *(const float4*)&B[(size_t)(k0 + brow) * N + bn + bcol];
        *(float4*)&Bs[brow + 8][bcol] = *(const float4*)&B[(size_t)(k0 + brow + 8) * N + bn + bcol];
        __syncthreads();
#pragma unroll
        for (int k = 0; k < 16; k++) {
            float a[8], b[8];
            *(float4*)&a[0] = *(float4*)&As[k][ty * 8];
            *(float4*)&a[4] = *(float4*)&As[k][ty * 8 + 4];
            *(float4*)&b[0] = *(float4*)&Bs[k][tx * 8];
            *(float4*)&b[4] = *(float4*)&Bs[k][tx * 8 + 4];
#pragma unroll
            for (int i = 0; i < 8; i++)
#pragma unroll
                for (int j = 0; j < 8; j++) acc[i][j] += a[i] * b[j];
        }
        __syncthreads();
    }

#pragma unroll
    for (int i = 0; i < 8; i++) {
        int row = bm + ty * 8 + i;
#pragma unroll
        for (int j = 0; j < 8; j += 4) {
            int col = bn + tx * 8 + j;
            float4 v;
            v.x = acc[i][j + 0] + bias[col + 0];
            v.y = acc[i][j + 1] + bias[col + 1];
            v.z = acc[i][j + 2] + bias[col + 2];
            v.w = acc[i][j + 3] + bias[col + 3];
            if (RELU) {
                v.x = fmaxf(v.x, 0.f); v.y = fmaxf(v.y, 0.f);
                v.z = fmaxf(v.z, 0.f); v.w = fmaxf(v.w, 0.f);
            }
            *(float4*)&C[(size_t)row * N + col] = v;
        }
    }
}

// ---------------- scores + top-k + counts ----------------
// grid: (NTOK/64, NH); block 256 threads.
// Computes scores[256 m][64 t] for one head/token-chunk, writes scores_div and
// gate_logits, then top-4 per token (warp per token), packed idx + histogram.
#define TCHUNK 64
__global__ __launch_bounds__(256) void scores_topk(
    const float* __restrict__ kv, const float* __restrict__ qslots,
    const float* __restrict__ mbias,
    float* __restrict__ out_scores, float* __restrict__ out_gate,
    unsigned int* __restrict__ idx_out, int* __restrict__ counts)
{
    extern __shared__ float smem[];
    float* q_s  = smem;                    // 256*33
    float* k_s  = q_s + 256 * 33;          // 64*33
    float* sc_s = k_s + 64 * 33;           // 256*65
    int*   hist = (int*)(sc_s + 256 * 65); // 256

    const int h  = blockIdx.y;
    const int n0 = blockIdx.x * TCHUNK;
    const int tid = threadIdx.x;

    hist[tid] = 0;

    const int tm = tid >> 2;   // 0..63 (m group of 4)
    const int tt = tid & 3;    // 0..3  (t group of 16)

    float acc[4][16];
#pragma unroll
    for (int i = 0; i < 4; i++)
#pragma unroll
        for (int j = 0; j < 16; j++) acc[i][j] = 0.f;

    for (int dc = 0; dc < HD; dc += 32) {
        // q tile: thread tid loads row m=tid, 32 d's
        {
            const float* src = &qslots[(size_t)tid * CORE + h * HD + dc];
#pragma unroll
            for (int j = 0; j < 32; j += 4) {
                float4 v = *(const float4*)&src[j];
                q_s[tid * 33 + j + 0] = v.x; q_s[tid * 33 + j + 1] = v.y;
                q_s[tid * 33 + j + 2] = v.z; q_s[tid * 33 + j + 3] = v.w;
            }
        }
        // k tile: t=tid/4, 8 d's at (tid%4)*8
        {
            int t = tid >> 2; int c = (tid & 3) * 8;
            const float* src = &kv[(size_t)(n0 + t) * CORE + h * HD + dc + c];
            float4 v0 = *(const float4*)src;
            float4 v1 = *(const float4*)(src + 4);
            k_s[t * 33 + c + 0] = v0.x; k_s[t * 33 + c + 1] = v0.y;
            k_s[t * 33 + c + 2] = v0.z; k_s[t * 33 + c + 3] = v0.w;
            k_s[t * 33 + c + 4] = v1.x; k_s[t * 33 + c + 5] = v1.y;
            k_s[t * 33 + c + 6] = v1.z; k_s[t * 33 + c + 7] = v1.w;
        }
        __syncthreads();
#pragma unroll 8
        for (int dd = 0; dd < 32; dd++) {
            float a[4], b[16];
#pragma unroll
            for (int i = 0; i < 4; i++) a[i] = q_s[(tm * 4 + i) * 33 + dd];
#pragma unroll
            for (int j = 0; j < 16; j++) b[j] = k_s[(tt * 16 + j) * 33 + dd];
#pragma unroll
            for (int i = 0; i < 4; i++)
#pragma unroll
                for (int j = 0; j < 16; j++) acc[i][j] += a[i] * b[j];
        }
        __syncthreads();
    }

    const float scale = 0.08838834764831845f; // 1/sqrt(128)
#pragma unroll
    for (int i = 0; i < 4; i++) {
        int m = tm * 4 + i;
        float bia = mbias[h * MSLOT + m] * 5.0f;
#pragma unroll
        for (int j = 0; j < 16; j++)
            sc_s[m * 65 + tt * 16 + j] = acc[i][j] * scale + bia;
    }
    __syncthreads();

    // coalesced global writes of both outputs
    size_t base = ((size_t)h * MSLOT) * NTOK + n0;
    {
        int t = tid & 63;
        int mo = tid >> 6;
        for (int r = 0; r < 64; r++) {
            int m = r * 4 + mo;
            float v = sc_s[m * 65 + t];
            out_scores[base + (size_t)m * NTOK + t] = v;
            out_gate  [base + (size_t)m * NTOK + t] = v;
        }
    }
    __syncthreads();

    // top-4 per token: warp per token (destroys sc_s)
    const int warp = tid >> 5, lane = tid & 31;
    for (int t = warp; t < TCHUNK; t += 8) {
        unsigned sel_pack = 0;
#pragma unroll
        for (int r = 0; r < TOPK; r++) {
            float bv = -3.402823466e38f; int bi = 0;
#pragma unroll
            for (int j = 0; j < 8; j++) {
                int m = lane + j * 32;
                float v = sc_s[m * 65 + t];
                if (v > bv) { bv = v; bi = m; }
            }
#pragma unroll
            for (int off = 16; off; off >>= 1) {
                float ov = __shfl_xor_sync(0xffffffffu, bv, off);
                int   oi = __shfl_xor_sync(0xffffffffu, bi, off);
                if (ov > bv || (ov == bv && oi < bi)) { bv = ov; bi = oi; }
            }
            if (lane == 0) sc_s[bi * 65 + t] = -3.402823466e38f;
            __syncwarp();
            sel_pack |= ((unsigned)bi) << (8 * r);
        }
        if (lane == 0) {
            idx_out[h * NTOK + n0 + t] = sel_pack;
            atomicAdd(&hist[sel_pack & 255], 1);
            atomicAdd(&hist[(sel_pack >> 8) & 255], 1);
            atomicAdd(&hist[(sel_pack >> 16) & 255], 1);
            atomicAdd(&hist[(sel_pack >> 24) & 255], 1);
        }
    }
    __syncthreads();
    if (hist[tid]) atomicAdd(&counts[h * MSLOT + tid], hist[tid]);
}

// ---------------- attended accumulation ----------------
// grid: (NTOK/1024, NH); block 256 threads; 128 KB smem accumulator [256][128].
// Warp w owns m in [w*32, w*32+32) -> race-free.
__global__ __launch_bounds__(256) void attend_accum(
    const float* __restrict__ kv, const unsigned int* __restrict__ idx,
    float* __restrict__ att)
{
    extern __shared__ float a_s[]; // 256*128
    const int h  = blockIdx.y;
    const int n0 = blockIdx.x * 1024;
    const int tid = threadIdx.x;
    for (int i = tid; i < MSLOT * HD; i += 256) a_s[i] = 0.f;
    __syncthreads();

    const int warp = tid >> 5, lane = tid & 31;
    const int mlo = warp * 32, mhi = mlo + 32;

    for (int t = 0; t < 1024; t++) {
        unsigned p = idx[h * NTOK + n0 + t];
        const float4* krow = (const float4*)&kv[(size_t)(n0 + t) * CORE + h * HD];
#pragma unroll
        for (int r = 0; r < TOPK; r++) {
            int m = (p >> (8 * r)) & 255;
            if (m >= mlo && m < mhi) {
                float4 kval = krow[lane];
                float4* dst = (float4*)&a_s[m * HD + lane * 4];
                float4 d = *dst;
                d.x += kval.x; d.y += kval.y; d.z += kval.z; d.w += kval.w;
                *dst = d;
            }
        }
    }
    __syncthreads();
    for (int i = tid; i < MSLOT * HD; i += 256) {
        float v = a_s[i];
        if (v != 0.f) atomicAdd(&att[(size_t)h * MSLOT * HD + i], v);
    }
}

// ---------------- build upd_in = concat(mem, context) ----------------
__global__ void build_updin(const float* __restrict__ mem,
                            const float* __restrict__ att,
                            float* __restrict__ out)
{
    int row = blockIdx.x, tid = threadIdx.x;
    for (int i = tid; i < 2 * CORE; i += 256) {
        float v;
        if (i < CORE) v = mem[(size_t)row * CORE + i];
        else {
            int c = i - CORE; int h = c >> 7, d = c & 127;
            v = att[(h << 15) + row * HD + d];
        }
        out[(size_t)row * 2 * CORE + i] = v;
    }
}

// ---------------- layernorm: one block per row, 256 threads ----------------
__global__ void ln_kernel(const float* __restrict__ x, const float* __restrict__ g,
                          const float* __restrict__ b, float* __restrict__ y, int L)
{
    int row = blockIdx.x, tid = threadIdx.x;
    const float* xr = &x[(size_t)row * L];
    float s = 0.f, s2 = 0.f;
    for (int i = tid; i < L; i += 256) { float v = xr[i]; s += v; s2 += v * v; }
    __shared__ float rs[8], rs2[8];
#pragma unroll
    for (int o = 16; o; o >>= 1) {
        s  += __shfl_xor_sync(0xffffffffu, s, o);
        s2 += __shfl_xor_sync(0xffffffffu, s2, o);
    }
    if ((tid & 31) == 0) { rs[tid >> 5] = s; rs2[tid >> 5] = s2; }
    __syncthreads();
    if (tid < 32) {
        s  = (tid < 8) ? rs[tid]  : 0.f;
        s2 = (tid < 8) ? rs2[tid] : 0.f;
#pragma unroll
        for (int o = 4; o; o >>= 1) {
            s  += __shfl_xor_sync(0xffffffffu, s, o);
            s2 += __shfl_xor_sync(0xffffffffu, s2, o);
        }
        if (tid == 0) { rs[0] = s; rs2[0] = s2; }
    }
    __syncthreads();
    float mu = rs[0] / (float)L;
    float var = rs2[0] / (float)L - mu * mu;
    float r = rsqrtf(var + 1e-5f);
    for (int i = tid; i < L; i += 256)
        y[(size_t)row * L + i] = (xr[i] - mu) * r * g[i] + b[i];
}

// ---------------- load fraction ----------------
__global__ void lf_kernel(const int* __restrict__ counts, float* __restrict__ out)
{
    int m = threadIdx.x;
    int s = 0;
#pragma unroll
    for (int h = 0; h < NH; h++) s += counts[h * MSLOT + m];
    out[m] = (float)s * 0.125f;
}

// ---------------- host launcher ----------------
extern "C" void kernel_launch(void* const* d_in, const int* in_sizes, int n_in,
                              void* d_out, int out_size)
{
    const float* bq_in   = (const float*)d_in[0];  // batch_queries [8,4096,2048]
    const float* mem     = (const float*)d_in[1];  // global_memory_base [1,256,1024]
    const float* Wq      = (const float*)d_in[2];
    const float* bq      = (const float*)d_in[3];
    const float* Ws1     = (const float*)d_in[4];
    const float* bs1     = (const float*)d_in[5];
    const float* Ws2     = (const float*)d_in[6];
    const float* bs2     = (const float*)d_in[7];
    const float* mbias   = (const float*)d_in[8];  // [8,256,1]
    const float* ln1_g   = (const float*)d_in[9];
    const float* ln1_b   = (const float*)d_in[10];
    const float* Wu1     = (const float*)d_in[11];
    const float* bu1     = (const float*)d_in[12];
    const float* Wu2     = (const float*)d_in[13];
    const float* bu2     = (const float*)d_in[14];
    const float* lno_g   = (const float*)d_in[15];
    const float* lno_b   = (const float*)d_in[16];

    float* out = (float*)d_out;
    float* out_dyn    = out;                              // 256*1024
    float* out_scores = out + (size_t)MSLOT * CORE;       // 8*256*32768
    float* out_gate   = out_scores + (size_t)NH * MSLOT * NTOK;
    float* out_lf     = out_gate + (size_t)NH * MSLOT * NTOK;

    void *p_kv, *p_hid, *p_qs, *p_att, *p_idx, *p_cnt, *p_ui, *p_h1, *p_hu, *p_h2;
    cudaGetSymbolAddress(&p_kv, g_kv);
    cudaGetSymbolAddress(&p_hid, g_hid);
    cudaGetSymbolAddress(&p_qs, g_qslots);
    cudaGetSymbolAddress(&p_att, g_att);
    cudaGetSymbolAddress(&p_idx, g_idx);
    cudaGetSymbolAddress(&p_cnt, g_counts);
    cudaGetSymbolAddress(&p_ui, g_updin);
    cudaGetSymbolAddress(&p_h1, g_h1);
    cudaGetSymbolAddress(&p_hu, g_hu);
    cudaGetSymbolAddress(&p_h2, g_h2);
    float* kv = (float*)p_kv;  float* hid = (float*)p_hid;
    float* qs = (float*)p_qs;  float* att = (float*)p_att;
    unsigned int* idxb = (unsigned int*)p_idx;
    int* cnt = (int*)p_cnt;
    float* ui = (float*)p_ui; float* h1 = (float*)p_h1;
    float* hu = (float*)p_hu; float* h2 = (float*)p_h2;

    // smem attributes (idempotent)
    int sm2 = (256 * 33 + 64 * 33 + 256 * 65 + 256) * 4;
    cudaFuncSetAttribute(scores_topk, cudaFuncAttributeMaxDynamicSharedMemorySize, sm2);
    int sm3 = MSLOT * HD * 4;
    cudaFuncSetAttribute(attend_accum, cudaFuncAttributeMaxDynamicSharedMemorySize, sm3);

    // zero accumulators
    cudaMemsetAsync(cnt, 0, NH * MSLOT * sizeof(int));
    cudaMemsetAsync(att, 0, NH * MSLOT * HD * sizeof(float));

    // 1) kv = flat @ Wq + bq   [32768,2048]x[2048,1024]
    sgemm_bias<false><<<dim3(CORE / 128, NTOK / 128), 256>>>(bq_in, Wq, bq, kv, NTOK, CORE, DM);

    // 2) q_slots MLP
    sgemm_bias<true ><<<dim3(INTER / 128, MSLOT / 128), 256>>>(mem, Ws1, bs1, hid, MSLOT, INTER, CORE);
    sgemm_bias<false><<<dim3(CORE / 128, MSLOT / 128), 256>>>(hid, Ws2, bs2, qs, MSLOT, CORE, INTER);

    // 3) scores + topk + counts
    scores_topk<<<dim3(NTOK / TCHUNK, NH), 256, sm2>>>(kv, qs, mbias, out_scores, out_gate, idxb, cnt);

    // 4) attended
    attend_accum<<<dim3(NTOK / 1024, NH), 256, sm3>>>(kv, idxb, att);

    // 5) update MLP
    build_updin<<<MSLOT, 256>>>(mem, att, ui);
    ln_kernel<<<MSLOT, 256>>>(ui, ln1_g, ln1_b, h1, 2 * CORE);
    sgemm_bias<true ><<<dim3(2 * CORE / 128, MSLOT / 128), 256>>>(h1, Wu1, bu1, hu, MSLOT, 2 * CORE, 2 * CORE);
    sgemm_bias<false><<<dim3(CORE / 128, MSLOT / 128), 256>>>(hu, Wu2, bu2, h2, MSLOT, CORE, 2 * CORE);
    ln_kernel<<<MSLOT, 256>>>(h2, lno_g, lno_b, out_dyn, CORE);

    // 6) load fraction
    lf_kernel<<<1, MSLOT>>>(cnt, out_lf);
}

// round 3
// speedup vs baseline: 1.4511x; 1.4511x over previous
#include <cuda_runtime.h>
#include <cuda_bf16.h>
#include <math.h>
#include <cstdint>

#define NTOK 32768
#define DM   2048
#define CORE 1024
#define MSLOT 256
#define NH   8
#define HD   128
#define INTER 4096
#define TOPK 4

// ---------------- scratch (device globals; no allocation) ----------------
__device__ float g_kv[NTOK * CORE];          // 128 MB
__device__ float g_hid[MSLOT * INTER];
__device__ float g_qslots[MSLOT * CORE];
__device__ float g_att[NH * MSLOT * HD];
__device__ unsigned int g_idx[NH * NTOK];    // packed 4 x u8 slot ids
__device__ int g_counts[NH * MSLOT];
__device__ float g_updin[MSLOT * 2 * CORE];
__device__ float g_h1[MSLOT * 2 * CORE];
__device__ float g_hu[MSLOT * 2 * CORE];
__device__ float g_h2[MSLOT * CORE];
__device__ __nv_bfloat16 g_BhiT[CORE * DM];  // Wq^T hi  [1024][2048]
__device__ __nv_bfloat16 g_BloT[CORE * DM];  // Wq^T lo

// ================= warp-MMA helpers (sm_80+ PTX only) =================
__device__ __forceinline__ uint32_t smem_u32(const void* p) {
    uint32_t a;
    asm("{ .reg .u64 t; cvta.to.shared.u64 t, %1; cvt.u32.u64 %0, t; }" : "=r"(a) : "l"(p));
    return a;
}
__device__ __forceinline__ void ldsm_x4(uint32_t& r0, uint32_t& r1, uint32_t& r2, uint32_t& r3, uint32_t addr) {
    asm volatile("ldmatrix.sync.aligned.m8n8.x4.shared.b16 {%0,%1,%2,%3}, [%4];"
                 : "=r"(r0), "=r"(r1), "=r"(r2), "=r"(r3) : "r"(addr));
}
__device__ __forceinline__ void mma_bf16(float* d, const uint32_t* a, const uint32_t* b) {
    asm volatile("mma.sync.aligned.m16n8k16.row.col.f32.bf16.bf16.f32 "
                 "{%0,%1,%2,%3}, {%4,%5,%6,%7}, {%8,%9}, {%0,%1,%2,%3};"
                 : "+f"(d[0]), "+f"(d[1]), "+f"(d[2]), "+f"(d[3])
                 : "r"(a[0]), "r"(a[1]), "r"(a[2]), "r"(a[3]), "r"(b[0]), "r"(b[1]));
}
__device__ __forceinline__ uint32_t sw128(uint32_t off) { return off ^ ((off >> 3) & 0x70); }

// ================= Wq transpose + bf16 hi/lo split =================
__global__ void transB_kernel(const float* __restrict__ W,
                              __nv_bfloat16* __restrict__ BhiT,
                              __nv_bfloat16* __restrict__ BloT)
{
    __shared__ float t[32][33];
    int n0 = blockIdx.x * 32, k0 = blockIdx.y * 32;
    int tx = threadIdx.x, ty = threadIdx.y;
#pragma unroll
    for (int i = 0; i < 4; i++)
        t[ty + i * 8][tx] = W[(size_t)(k0 + ty + i * 8) * CORE + n0 + tx];
    __syncthreads();
#pragma unroll
    for (int i = 0; i < 4; i++) {
        int n = n0 + ty + i * 8, k = k0 + tx;
        float v = t[tx][ty + i * 8];
        __nv_bfloat16 hi = __float2bfloat16_rn(v);
        float lo = v - __bfloat162float(hi);
        BhiT[(size_t)n * DM + k] = hi;
        BloT[(size_t)n * DM + k] = __float2bfloat16_rn(lo);
    }
}

// ================= kv GEMM: HMMA bf16 split-precision =================
// C[32768,1024] = A[32768,2048] @ Wq[2048,1024] + bias
// CTA 128x128, 8 warps (4m x 2n), warp tile 32x64, K-chunk 32.
// Smem rows 128B: bytes [0,64) = hi (32 bf16), [64,128) = lo. SW128 swizzle.
#define KCH 32
#define NCH (DM / KCH)        // 64
#define OPTILE 16384          // 128 rows x 128B

__global__ __launch_bounds__(256) void kv_gemm_mma(
    const float* __restrict__ A,
    const __nv_bfloat16* __restrict__ BhiT, const __nv_bfloat16* __restrict__ BloT,
    const float* __restrict__ bias, float* __restrict__ C)
{
    extern __shared__ char smem[];
    const int tid = threadIdx.x;
    const int wid = tid >> 5, lane = tid & 31;
    const int wm = wid & 3, wn = wid >> 2;
    const int bm = blockIdx.y * 128;
    const int bn = blockIdx.x * 128;

    uint32_t sbase = smem_u32(smem);
    uint32_t s0 = (sbase + 1023u) & ~1023u;           // aligned base
    char* smc = smem + (s0 - sbase);
    // buffers: buf b: A tile at b*2*OPTILE, B tile at b*2*OPTILE + OPTILE

    const int lrow  = tid >> 1;     // 0..127
    const int lhalf = tid & 1;      // k half (16 elems)

    // precomputed sts offsets (swizzled)
    const uint32_t stoff0 = sw128(lrow * 128 + lhalf * 32);
    const uint32_t stoff1 = sw128(lrow * 128 + lhalf * 32 + 16);
    const uint32_t stoff0L = sw128(lrow * 128 + 64 + lhalf * 32);
    const uint32_t stoff1L = sw128(lrow * 128 + 64 + lhalf * 32 + 16);

    // ldmatrix per-lane geometry
    const int g = lane >> 3, r = lane & 7;
    const int a_m  = wm * 32 + (g & 1) * 8 + r;        // + mb*16
    const int a_kb = (g >> 1) * 16;                    // + ks*32 (+64 lo)
    const int b_n  = wn * 64 + ((g >> 1) & 1) * 8 + r; // + p*16
    const int b_kb = (g & 1) * 16;

    float acc[2][8][4];
#pragma unroll
    for (int mb = 0; mb < 2; mb++)
#pragma unroll
        for (int nb = 0; nb < 8; nb++)
#pragma unroll
            for (int q = 0; q < 4; q++) acc[mb][nb][q] = 0.f;

    float4 av[4];          // A staging (16 fp32)
    float4 bhv[2], blv[2]; // B staging (32 bf16 each)

    // ---- load chunk 0 ----
    {
        const float* ap = &A[(size_t)(bm + lrow) * DM + lhalf * 16];
#pragma unroll
        for (int j = 0; j < 4; j++) av[j] = *(const float4*)(ap + 4 * j);
        const __nv_bfloat16* bhp = &BhiT[(size_t)(bn + lrow) * DM + lhalf * 16];
        const __nv_bfloat16* blp = &BloT[(size_t)(bn + lrow) * DM + lhalf * 16];
        bhv[0] = *(const float4*)bhp; bhv[1] = *(const float4*)(bhp + 8);
        blv[0] = *(const float4*)blp; blv[1] = *(const float4*)(blp + 8);
    }

    for (int c = 0; c < NCH; c++) {
        const int buf = c & 1;
        char* tA = smc + buf * 2 * OPTILE;
        char* tB = tA + OPTILE;

        // ---- sts staged chunk c into buf ----
        {
            __nv_bfloat162 h[8], l[8];
#pragma unroll
            for (int j = 0; j < 4; j++) {
                float f0 = av[j].x, f1 = av[j].y, f2 = av[j].z, f3 = av[j].w;
                __nv_bfloat16 h0 = __float2bfloat16_rn(f0), h1 = __float2bfloat16_rn(f1);
                __nv_bfloat16 h2 = __float2bfloat16_rn(f2), h3 = __float2bfloat16_rn(f3);
                h[2 * j].x = h0; h[2 * j].y = h1; h[2 * j + 1].x = h2; h[2 * j + 1].y = h3;
                l[2 * j].x = __float2bfloat16_rn(f0 - __bfloat162float(h0));
                l[2 * j].y = __float2bfloat16_rn(f1 - __bfloat162float(h1));
                l[2 * j + 1].x = __float2bfloat16_rn(f2 - __bfloat162float(h2));
                l[2 * j + 1].y = __float2bfloat16_rn(f3 - __bfloat162float(h3));
            }
            *(uint4*)(tA + stoff0)  = *(uint4*)&h[0];
            *(uint4*)(tA + stoff1)  = *(uint4*)&h[4];
            *(uint4*)(tA + stoff0L) = *(uint4*)&l[0];
            *(uint4*)(tA + stoff1L) = *(uint4*)&l[4];
            *(float4*)(tB + stoff0)  = bhv[0];
            *(float4*)(tB + stoff1)  = bhv[1];
            *(float4*)(tB + stoff0L) = blv[0];
            *(float4*)(tB + stoff1L) = blv[1];
        }
        __syncthreads();

        // ---- prefetch chunk c+1 ----
        if (c + 1 < NCH) {
            const int kc = (c + 1) * KCH;
            const float* ap = &A[(size_t)(bm + lrow) * DM + kc + lhalf * 16];
#pragma unroll
            for (int j = 0; j < 4; j++) av[j] = *(const float4*)(ap + 4 * j);
            const __nv_bfloat16* bhp = &BhiT[(size_t)(bn + lrow) * DM + kc + lhalf * 16];
            const __nv_bfloat16* blp = &BloT[(size_t)(bn + lrow) * DM + kc + lhalf * 16];
            bhv[0] = *(const float4*)bhp; bhv[1] = *(const float4*)(bhp + 8);
            blv[0] = *(const float4*)blp; blv[1] = *(const float4*)(blp + 8);
        }

        // ---- compute chunk c ----
        const uint32_t tAu = s0 + buf * 2 * OPTILE;
        const uint32_t tBu = tAu + OPTILE;
#pragma unroll
        for (int ks = 0; ks < 2; ks++) {
            uint32_t ah[2][4], al[2][4];
#pragma unroll
            for (int mb = 0; mb < 2; mb++) {
                uint32_t offH = sw128((a_m + mb * 16) * 128 + ks * 32 + a_kb);
                uint32_t offL = sw128((a_m + mb * 16) * 128 + 64 + ks * 32 + a_kb);
                ldsm_x4(ah[mb][0], ah[mb][1], ah[mb][2], ah[mb][3], tAu + offH);
                ldsm_x4(al[mb][0], al[mb][1], al[mb][2], al[mb][3], tAu + offL);
            }
#pragma unroll
            for (int p = 0; p < 4; p++) {
                uint32_t bh[4], bl[4];
                uint32_t offH = sw128((b_n + p * 16) * 128 + ks * 32 + b_kb);
                uint32_t offL = sw128((b_n + p * 16) * 128 + 64 + ks * 32 + b_kb);
                ldsm_x4(bh[0], bh[1], bh[2], bh[3], tBu + offH);
                ldsm_x4(bl[0], bl[1], bl[2], bl[3], tBu + offL);
#pragma unroll
                for (int mb = 0; mb < 2; mb++) {
#pragma unroll
                    for (int half = 0; half < 2; half++) {
                        float* d = acc[mb][p * 2 + half];
                        mma_bf16(d, ah[mb], &bh[half * 2]);
                        mma_bf16(d, ah[mb], &bl[half * 2]);
                        mma_bf16(d, al[mb], &bh[half * 2]);
                    }
                }
            }
        }
        __syncthreads();
    }

    // ---- epilogue ----
#pragma unroll
    for (int mb = 0; mb < 2; mb++) {
        int row0 = bm + wm * 32 + mb * 16 + (lane >> 2);
#pragma unroll
        for (int nb = 0; nb < 8; nb++) {
            int col = bn + wn * 64 + nb * 8 + (lane & 3) * 2;
            float2 b2 = *(const float2*)&bias[col];
            float2 v0 = make_float2(acc[mb][nb][0] + b2.x, acc[mb][nb][1] + b2.y);
            float2 v1 = make_float2(acc[mb][nb][2] + b2.x, acc[mb][nb][3] + b2.y);
            *(float2*)&C[(size_t)row0 * CORE + col] = v0;
            *(float2*)&C[(size_t)(row0 + 8) * CORE + col] = v1;
        }
    }
}

// ---------------- generic SGEMM: C = A[MxK] @ B[KxN] + bias, opt relu ----
template <bool RELU>
__global__ __launch_bounds__(256) void sgemm_bias(
    const float* __restrict__ A, const float* __restrict__ B,
    const float* __restrict__ bias, float* __restrict__ C,
    int M, int N, int K)
{
    __shared__ float As[16][128];
    __shared__ float Bs[16][128];

    const int tid = threadIdx.x;
    const int bm = blockIdx.y * 128;
    const int bn = blockIdx.x * 128;
    const int tx = tid & 15;
    const int ty = tid >> 4;

    const int arow = tid >> 2;
    const int acol = (tid & 3) * 4;
    const int brow = tid >> 5;
    const int bcol = (tid & 31) * 4;

    float acc[8][8];
#pragma unroll
    for (int i = 0; i < 8; i++)
#pragma unroll
        for (int j = 0; j < 8; j++) acc[i][j] = 0.f;

    for (int k0 = 0; k0 < K; k0 += 16) {
        float4 a0 = *(const float4*)&A[(size_t)(bm + arow) * K + k0 + acol];
        float4 a1 = *(const float4*)&A[(size_t)(bm + arow + 64) * K + k0 + acol];
        As[acol + 0][arow] = a0.x; As[acol + 1][arow] = a0.y;
        As[acol + 2][arow] = a0.z; As[acol + 3][arow] = a0.w;
        As[acol + 0][arow + 64] = a1.x; As[acol + 1][arow + 64] = a1.y;
        As[acol + 2][arow + 64] = a1.z; As[acol + 3][arow + 64] = a1.w;
        *(float4*)&Bs[brow][bcol]     = *(const float4*)&B[(size_t)(k0 + brow) * N + bn + bcol];
        *(float4*)&Bs[brow + 8][bcol] = *(const float4*)&B[(size_t)(k0 + brow + 8) * N + bn + bcol];
        __syncthreads();
#pragma unroll
        for (int k = 0; k < 16; k++) {
            float a[8], b[8];
            *(float4*)&a[0] = *(float4*)&As[k][ty * 8];
            *(float4*)&a[4] = *(float4*)&As[k][ty * 8 + 4];
            *(float4*)&b[0] = *(float4*)&Bs[k][tx * 8];
            *(float4*)&b[4] = *(float4*)&Bs[k][tx * 8 + 4];
#pragma unroll
            for (int i = 0; i < 8; i++)
#pragma unroll
                for (int j = 0; j < 8; j++) acc[i][j] += a[i] * b[j];
        }
        __syncthreads();
    }

#pragma unroll
    for (int i = 0; i < 8; i++) {
        int row = bm + ty * 8 + i;
#pragma unroll
        for (int j = 0; j < 8; j += 4) {
            int col = bn + tx * 8 + j;
            float4 v;
            v.x = acc[i][j + 0] + bias[col + 0];
            v.y = acc[i][j + 1] + bias[col + 1];
            v.z = acc[i][j + 2] + bias[col + 2];
            v.w = acc[i][j + 3] + bias[col + 3];
            if (RELU) {
                v.x = fmaxf(v.x, 0.f); v.y = fmaxf(v.y, 0.f);
                v.z = fmaxf(v.z, 0.f); v.w = fmaxf(v.w, 0.f);
            }
            *(float4*)&C[(size_t)row * N + col] = v;
        }
    }
}

// ---------------- scores + top-k + counts ----------------
#define TCHUNK 64
__global__ __launch_bounds__(256) void scores_topk(
    const float* __restrict__ kv, const float* __restrict__ qslots,
    const float* __restrict__ mbias,
    float* __restrict__ out_scores, float* __restrict__ out_gate,
    unsigned int* __restrict__ idx_out, int* __restrict__ counts)
{
    extern __shared__ float smemf[];
    float* q_s  = smemf;
    float* k_s  = q_s + 256 * 33;
    float* sc_s = k_s + 64 * 33;
    int*   hist = (int*)(sc_s + 256 * 65);

    const int h  = blockIdx.y;
    const int n0 = blockIdx.x * TCHUNK;
    const int tid = threadIdx.x;

    hist[tid] = 0;

    const int tm = tid >> 2;
    const int tt = tid & 3;

    float acc[4][16];
#pragma unroll
    for (int i = 0; i < 4; i++)
#pragma unroll
        for (int j = 0; j < 16; j++) acc[i][j] = 0.f;

    for (int dc = 0; dc < HD; dc += 32) {
        {
            const float* src = &qslots[(size_t)tid * CORE + h * HD + dc];
#pragma unroll
            for (int j = 0; j < 32; j += 4) {
                float4 v = *(const float4*)&src[j];
                q_s[tid * 33 + j + 0] = v.x; q_s[tid * 33 + j + 1] = v.y;
                q_s[tid * 33 + j + 2] = v.z; q_s[tid * 33 + j + 3] = v.w;
            }
        }
        {
            int t = tid >> 2; int cc = (tid & 3) * 8;
            const float* src = &kv[(size_t)(n0 + t) * CORE + h * HD + dc + cc];
            float4 v0 = *(const float4*)src;
            float4 v1 = *(const float4*)(src + 4);
            k_s[t * 33 + cc + 0] = v0.x; k_s[t * 33 + cc + 1] = v0.y;
            k_s[t * 33 + cc + 2] = v0.z; k_s[t * 33 + cc + 3] = v0.w;
            k_s[t * 33 + cc + 4] = v1.x; k_s[t * 33 + cc + 5] = v1.y;
            k_s[t * 33 + cc + 6] = v1.z; k_s[t * 33 + cc + 7] = v1.w;
        }
        __syncthreads();
#pragma unroll 8
        for (int dd = 0; dd < 32; dd++) {
            float a[4], b[16];
#pragma unroll
            for (int i = 0; i < 4; i++) a[i] = q_s[(tm * 4 + i) * 33 + dd];
#pragma unroll
            for (int j = 0; j < 16; j++) b[j] = k_s[(tt * 16 + j) * 33 + dd];
#pragma unroll
            for (int i = 0; i < 4; i++)
#pragma unroll
                for (int j = 0; j < 16; j++) acc[i][j] += a[i] * b[j];
        }
        __syncthreads();
    }

    const float scale = 0.08838834764831845f;
#pragma unroll
    for (int i = 0; i < 4; i++) {
        int m = tm * 4 + i;
        float bia = mbias[h * MSLOT + m] * 5.0f;
#pragma unroll
        for (int j = 0; j < 16; j++)
            sc_s[m * 65 + tt * 16 + j] = acc[i][j] * scale + bia;
    }
    __syncthreads();

    size_t base = ((size_t)h * MSLOT) * NTOK + n0;
    {
        int t = tid & 63;
        int mo = tid >> 6;
        for (int rr = 0; rr < 64; rr++) {
            int m = rr * 4 + mo;
            float v = sc_s[m * 65 + t];
            out_scores[base + (size_t)m * NTOK + t] = v;
            out_gate  [base + (size_t)m * NTOK + t] = v;
        }
    }
    __syncthreads();

    const int warp = tid >> 5, lane = tid & 31;
    for (int t = warp; t < TCHUNK; t += 8) {
        unsigned sel_pack = 0;
#pragma unroll
        for (int rr = 0; rr < TOPK; rr++) {
            float bv = -3.402823466e38f; int bi = 0;
#pragma unroll
            for (int j = 0; j < 8; j++) {
                int m = lane + j * 32;
                float v = sc_s[m * 65 + t];
                if (v > bv) { bv = v; bi = m; }
            }
#pragma unroll
            for (int off = 16; off; off >>= 1) {
                float ov = __shfl_xor_sync(0xffffffffu, bv, off);
                int   oi = __shfl_xor_sync(0xffffffffu, bi, off);
                if (ov > bv || (ov == bv && oi < bi)) { bv = ov; bi = oi; }
            }
            if (lane == 0) sc_s[bi * 65 + t] = -3.402823466e38f;
            __syncwarp();
            sel_pack |= ((unsigned)bi) << (8 * rr);
        }
        if (lane == 0) {
            idx_out[h * NTOK + n0 + t] = sel_pack;
            atomicAdd(&hist[sel_pack & 255], 1);
            atomicAdd(&hist[(sel_pack >> 8) & 255], 1);
            atomicAdd(&hist[(sel_pack >> 16) & 255], 1);
            atomicAdd(&hist[(sel_pack >> 24) & 255], 1);
        }
    }
    __syncthreads();
    if (hist[tid]) atomicAdd(&counts[h * MSLOT + tid], hist[tid]);
}

// ---------------- attended accumulation ----------------
__global__ __launch_bounds__(256) void attend_accum(
    const float* __restrict__ kv, const unsigned int* __restrict__ idx,
    float* __restrict__ att)
{
    extern __shared__ float a_s[];
    const int h  = blockIdx.y;
    const int n0 = blockIdx.x * 1024;
    const int tid = threadIdx.x;
    for (int i = tid; i < MSLOT * HD; i += 256) a_s[i] = 0.f;
    __syncthreads();

    const int warp = tid >> 5, lane = tid & 31;
    const int mlo = warp * 32, mhi = mlo + 32;

    for (int t = 0; t < 1024; t++) {
        unsigned p = idx[h * NTOK + n0 + t];
        const float4* krow = (const float4*)&kv[(size_t)(n0 + t) * CORE + h * HD];
#pragma unroll
        for (int r = 0; r < TOPK; r++) {
            int m = (p >> (8 * r)) & 255;
            if (m >= mlo && m < mhi) {
                float4 kval = krow[lane];
                float4* dst = (float4*)&a_s[m * HD + lane * 4];
                float4 d = *dst;
                d.x += kval.x; d.y += kval.y; d.z += kval.z; d.w += kval.w;
                *dst = d;
            }
        }
    }
    __syncthreads();
    for (int i = tid; i < MSLOT * HD; i += 256) {
        float v = a_s[i];
        if (v != 0.f) atomicAdd(&att[(size_t)h * MSLOT * HD + i], v);
    }
}

// ---------------- build upd_in = concat(mem, context) ----------------
__global__ void build_updin(const float* __restrict__ mem,
                            const float* __restrict__ att,
                            float* __restrict__ out)
{
    int row = blockIdx.x, tid = threadIdx.x;
    for (int i = tid; i < 2 * CORE; i += 256) {
        float v;
        if (i < CORE) v = mem[(size_t)row * CORE + i];
        else {
            int c = i - CORE; int h = c >> 7, d = c & 127;
            v = att[(h << 15) + row * HD + d];
        }
        out[(size_t)row * 2 * CORE + i] = v;
    }
}

// ---------------- layernorm ----------------
__global__ void ln_kernel(const float* __restrict__ x, const float* __restrict__ g,
                          const float* __restrict__ b, float* __restrict__ y, int L)
{
    int row = blockIdx.x, tid = threadIdx.x;
    const float* xr = &x[(size_t)row * L];
    float s = 0.f, s2 = 0.f;
    for (int i = tid; i < L; i += 256) { float v = xr[i]; s += v; s2 += v * v; }
    __shared__ float rs[8], rs2[8];
#pragma unroll
    for (int o = 16; o; o >>= 1) {
        s  += __shfl_xor_sync(0xffffffffu, s, o);
        s2 += __shfl_xor_sync(0xffffffffu, s2, o);
    }
    if ((tid & 31) == 0) { rs[tid >> 5] = s; rs2[tid >> 5] = s2; }
    __syncthreads();
    if (tid < 32) {
        s  = (tid < 8) ? rs[tid]  : 0.f;
        s2 = (tid < 8) ? rs2[tid] : 0.f;
#pragma unroll
        for (int o = 4; o; o >>= 1) {
            s  += __shfl_xor_sync(0xffffffffu, s, o);
            s2 += __shfl_xor_sync(0xffffffffu, s2, o);
        }
        if (tid == 0) { rs[0] = s; rs2[0] = s2; }
    }
    __syncthreads();
    float mu = rs[0] / (float)L;
    float var = rs2[0] / (float)L - mu * mu;
    float r = rsqrtf(var + 1e-5f);
    for (int i = tid; i < L; i += 256)
        y[(size_t)row * L + i] = (xr[i] - mu) * r * g[i] + b[i];
}

// ---------------- load fraction ----------------
__global__ void lf_kernel(const int* __restrict__ counts, float* __restrict__ out)
{
    int m = threadIdx.x;
    int s = 0;
#pragma unroll
    for (int h = 0; h < NH; h++) s += counts[h * MSLOT + m];
    out[m] = (float)s * 0.125f;
}

// ---------------- host launcher ----------------
extern "C" void kernel_launch(void* const* d_in, const int* in_sizes, int n_in,
                              void* d_out, int out_size)
{
    const float* bq_in   = (const float*)d_in[0];
    const float* mem     = (const float*)d_in[1];
    const float* Wq      = (const float*)d_in[2];
    const float* bq      = (const float*)d_in[3];
    const float* Ws1     = (const float*)d_in[4];
    const float* bs1     = (const float*)d_in[5];
    const float* Ws2     = (const float*)d_in[6];
    const float* bs2     = (const float*)d_in[7];
    const float* mbias   = (const float*)d_in[8];
    const float* ln1_g   = (const float*)d_in[9];
    const float* ln1_b   = (const float*)d_in[10];
    const float* Wu1     = (const float*)d_in[11];
    const float* bu1     = (const float*)d_in[12];
    const float* Wu2     = (const float*)d_in[13];
    const float* bu2     = (const float*)d_in[14];
    const float* lno_g   = (const float*)d_in[15];
    const float* lno_b   = (const float*)d_in[16];

    float* out = (float*)d_out;
    float* out_dyn    = out;
    float* out_scores = out + (size_t)MSLOT * CORE;
    float* out_gate   = out_scores + (size_t)NH * MSLOT * NTOK;
    float* out_lf     = out_gate + (size_t)NH * MSLOT * NTOK;

    void *p_kv, *p_hid, *p_qs, *p_att, *p_idx, *p_cnt, *p_ui, *p_h1, *p_hu, *p_h2, *p_bh, *p_bl;
    cudaGetSymbolAddress(&p_kv, g_kv);
    cudaGetSymbolAddress(&p_hid, g_hid);
    cudaGetSymbolAddress(&p_qs, g_qslots);
    cudaGetSymbolAddress(&p_att, g_att);
    cudaGetSymbolAddress(&p_idx, g_idx);
    cudaGetSymbolAddress(&p_cnt, g_counts);
    cudaGetSymbolAddress(&p_ui, g_updin);
    cudaGetSymbolAddress(&p_h1, g_h1);
    cudaGetSymbolAddress(&p_hu, g_hu);
    cudaGetSymbolAddress(&p_h2, g_h2);
    cudaGetSymbolAddress(&p_bh, g_BhiT);
    cudaGetSymbolAddress(&p_bl, g_BloT);
    float* kv = (float*)p_kv;  float* hid = (float*)p_hid;
    float* qs = (float*)p_qs;  float* att = (float*)p_att;
    unsigned int* idxb = (unsigned int*)p_idx;
    int* cnt = (int*)p_cnt;
    float* ui = (float*)p_ui; float* h1 = (float*)p_h1;
    float* hu = (float*)p_hu; float* h2 = (float*)p_h2;
    __nv_bfloat16* BhiT = (__nv_bfloat16*)p_bh;
    __nv_bfloat16* BloT = (__nv_bfloat16*)p_bl;

    int sm2 = (256 * 33 + 64 * 33 + 256 * 65 + 256) * 4;
    cudaFuncSetAttribute(scores_topk, cudaFuncAttributeMaxDynamicSharedMemorySize, sm2);
    int sm3 = MSLOT * HD * 4;
    cudaFuncSetAttribute(attend_accum, cudaFuncAttributeMaxDynamicSharedMemorySize, sm3);
    int smg = 4 * OPTILE + 1024;  // 64KB + align pad
    cudaFuncSetAttribute(kv_gemm_mma, cudaFuncAttributeMaxDynamicSharedMemorySize, smg);

    cudaMemsetAsync(cnt, 0, NH * MSLOT * sizeof(int));
    cudaMemsetAsync(att, 0, NH * MSLOT * HD * sizeof(float));

    // 0) Wq transpose + bf16 split
    transB_kernel<<<dim3(CORE / 32, DM / 32), dim3(32, 8)>>>(Wq, BhiT, BloT);

    // 1) kv = flat @ Wq + bq via HMMA split-precision
    kv_gemm_mma<<<dim3(CORE / 128, NTOK / 128), 256, smg>>>(bq_in, BhiT, BloT, bq, kv);

    // 2) q_slots MLP
    sgemm_bias<true ><<<dim3(INTER / 128, MSLOT / 128), 256>>>(mem, Ws1, bs1, hid, MSLOT, INTER, CORE);
    sgemm_bias<false><<<dim3(CORE / 128, MSLOT / 128), 256>>>(hid, Ws2, bs2, qs, MSLOT, CORE, INTER);

    // 3) scores + topk + counts
    scores_topk<<<dim3(NTOK / TCHUNK, NH), 256, sm2>>>(kv, qs, mbias, out_scores, out_gate, idxb, cnt);

    // 4) attended
    attend_accum<<<dim3(NTOK / 1024, NH), 256, sm3>>>(kv, idxb, att);

    // 5) update MLP
    build_updin<<<MSLOT, 256>>>(mem, att, ui);
    ln_kernel<<<MSLOT, 256>>>(ui, ln1_g, ln1_b, h1, 2 * CORE);
    sgemm_bias<true ><<<dim3(2 * CORE / 128, MSLOT / 128), 256>>>(h1, Wu1, bu1, hu, MSLOT, 2 * CORE, 2 * CORE);
    sgemm_bias<false><<<dim3(CORE / 128, MSLOT / 128), 256>>>(hu, Wu2, bu2, h2, MSLOT, CORE, 2 * CORE);
    ln_kernel<<<MSLOT, 256>>>(h2, lno_g, lno_b, out_dyn, CORE);

    // 6) load fraction
    lf_kernel<<<1, MSLOT>>>(cnt, out_lf);
}

// round 4
// speedup vs baseline: 1.9884x; 1.3702x over previous
#include <cuda_runtime.h>
#include <cuda_bf16.h>
#include <math.h>
#include <cstdint>

#define NTOK 32768
#define DM   2048
#define CORE 1024
#define MSLOT 256
#define NH   8
#define HD   128
#define INTER 4096
#define TOPK 4

// ---------------- scratch (device globals; no allocation) ----------------
__device__ float g_kv[NTOK * CORE];          // 128 MB
__device__ float g_hid[MSLOT * INTER];
__device__ float g_qslots[MSLOT * CORE];
__device__ float g_att[NH * MSLOT * HD];
__device__ unsigned int g_idx[NH * NTOK];
__device__ int g_counts[NH * MSLOT];
__device__ float g_updin[MSLOT * 2 * CORE];
__device__ float g_h1[MSLOT * 2 * CORE];
__device__ float g_hu[MSLOT * 2 * CORE];
__device__ float g_h2[MSLOT * CORE];
__device__ float g_part[MSLOT * 16384];      // split-K partials (16 MB)
__device__ __nv_bfloat16 g_BhiT[CORE * DM];  // Wq^T hi
__device__ __nv_bfloat16 g_BloT[CORE * DM];  // Wq^T lo
__device__ __nv_bfloat16 g_W1h[INTER * CORE], g_W1l[INTER * CORE];       // Ws1^T
__device__ __nv_bfloat16 g_W2h[CORE * INTER], g_W2l[CORE * INTER];       // Ws2^T
__device__ __nv_bfloat16 g_U1h[2*CORE * 2*CORE], g_U1l[2*CORE * 2*CORE]; // Wu1^T
__device__ __nv_bfloat16 g_U2h[CORE * 2*CORE], g_U2l[CORE * 2*CORE];     // Wu2^T

// ================= warp-MMA helpers (sm_80+ PTX only) =================
__device__ __forceinline__ uint32_t smem_u32(const void* p) {
    uint32_t a;
    asm("{ .reg .u64 t; cvta.to.shared.u64 t, %1; cvt.u32.u64 %0, t; }" : "=r"(a) : "l"(p));
    return a;
}
__device__ __forceinline__ void ldsm_x4(uint32_t& r0, uint32_t& r1, uint32_t& r2, uint32_t& r3, uint32_t addr) {
    asm volatile("ldmatrix.sync.aligned.m8n8.x4.shared.b16 {%0,%1,%2,%3}, [%4];"
                 : "=r"(r0), "=r"(r1), "=r"(r2), "=r"(r3) : "r"(addr));
}
__device__ __forceinline__ void mma_bf16(float* d, const uint32_t* a, const uint32_t* b) {
    asm volatile("mma.sync.aligned.m16n8k16.row.col.f32.bf16.bf16.f32 "
                 "{%0,%1,%2,%3}, {%4,%5,%6,%7}, {%8,%9}, {%0,%1,%2,%3};"
                 : "+f"(d[0]), "+f"(d[1]), "+f"(d[2]), "+f"(d[3])
                 : "r"(a[0]), "r"(a[1]), "r"(a[2]), "r"(a[3]), "r"(b[0]), "r"(b[1]));
}
__device__ __forceinline__ uint32_t sw128(uint32_t off) { return off ^ ((off >> 3) & 0x70); }

// ================= generic W[K,N] -> W^T hi/lo split =================
__global__ void transB_gen(const float* __restrict__ W,
                           __nv_bfloat16* __restrict__ BhiT,
                           __nv_bfloat16* __restrict__ BloT, int K, int N)
{
    __shared__ float t[32][33];
    int n0 = blockIdx.x * 32, k0 = blockIdx.y * 32;
    int tx = threadIdx.x, ty = threadIdx.y;
#pragma unroll
    for (int i = 0; i < 4; i++)
        t[ty + i * 8][tx] = W[(size_t)(k0 + ty + i * 8) * N + n0 + tx];
    __syncthreads();
#pragma unroll
    for (int i = 0; i < 4; i++) {
        int n = n0 + ty + i * 8, k = k0 + tx;
        float v = t[tx][ty + i * 8];
        __nv_bfloat16 hi = __float2bfloat16_rn(v);
        float lo = v - __bfloat162float(hi);
        BhiT[(size_t)n * K + k] = hi;
        BloT[(size_t)n * K + k] = __float2bfloat16_rn(lo);
    }
}

// ================= HMMA split-bf16 GEMM body (macro-free shared impl) ====
// CTA 128x128, 8 warps (4m x 2n), K-chunk 32, double-buffered smem.
#define KCH 32
#define OPTILE 16384          // 128 rows x 128B

// kv GEMM: full K in one CTA (K=2048), bias fused.
__global__ __launch_bounds__(256) void kv_gemm_mma(
    const float* __restrict__ A,
    const __nv_bfloat16* __restrict__ BhiT, const __nv_bfloat16* __restrict__ BloT,
    const float* __restrict__ bias, float* __restrict__ C)
{
    extern __shared__ char smem[];
    const int tid = threadIdx.x;
    const int wid = tid >> 5, lane = tid & 31;
    const int wm = wid & 3, wn = wid >> 2;
    const int bm = blockIdx.y * 128;
    const int bn = blockIdx.x * 128;
    const int NCH = DM / KCH;

    uint32_t sbase = smem_u32(smem);
    uint32_t s0 = (sbase + 1023u) & ~1023u;
    char* smc = smem + (s0 - sbase);

    const int lrow  = tid >> 1;
    const int lhalf = tid & 1;
    const uint32_t stoff0  = sw128(lrow * 128 + lhalf * 32);
    const uint32_t stoff1  = sw128(lrow * 128 + lhalf * 32 + 16);
    const uint32_t stoff0L = sw128(lrow * 128 + 64 + lhalf * 32);
    const uint32_t stoff1L = sw128(lrow * 128 + 64 + lhalf * 32 + 16);

    const int g = lane >> 3, r = lane & 7;
    const int a_m  = wm * 32 + (g & 1) * 8 + r;
    const int a_kb = (g >> 1) * 16;
    const int b_n  = wn * 64 + ((g >> 1) & 1) * 8 + r;
    const int b_kb = (g & 1) * 16;

    float acc[2][8][4];
#pragma unroll
    for (int mb = 0; mb < 2; mb++)
#pragma unroll
        for (int nb = 0; nb < 8; nb++)
#pragma unroll
            for (int q = 0; q < 4; q++) acc[mb][nb][q] = 0.f;

    float4 av[4];
    float4 bhv[2], blv[2];
    {
        const float* ap = &A[(size_t)(bm + lrow) * DM + lhalf * 16];
#pragma unroll
        for (int j = 0; j < 4; j++) av[j] = *(const float4*)(ap + 4 * j);
        const __nv_bfloat16* bhp = &BhiT[(size_t)(bn + lrow) * DM + lhalf * 16];
        const __nv_bfloat16* blp = &BloT[(size_t)(bn + lrow) * DM + lhalf * 16];
        bhv[0] = *(const float4*)bhp; bhv[1] = *(const float4*)(bhp + 8);
        blv[0] = *(const float4*)blp; blv[1] = *(const float4*)(blp + 8);
    }

    for (int c = 0; c < NCH; c++) {
        const int buf = c & 1;
        char* tA = smc + buf * 2 * OPTILE;
        char* tB = tA + OPTILE;
        {
            __nv_bfloat162 h[8], l[8];
#pragma unroll
            for (int j = 0; j < 4; j++) {
                float f0 = av[j].x, f1 = av[j].y, f2 = av[j].z, f3 = av[j].w;
                __nv_bfloat16 h0 = __float2bfloat16_rn(f0), h1 = __float2bfloat16_rn(f1);
                __nv_bfloat16 h2 = __float2bfloat16_rn(f2), h3 = __float2bfloat16_rn(f3);
                h[2 * j].x = h0; h[2 * j].y = h1; h[2 * j + 1].x = h2; h[2 * j + 1].y = h3;
                l[2 * j].x = __float2bfloat16_rn(f0 - __bfloat162float(h0));
                l[2 * j].y = __float2bfloat16_rn(f1 - __bfloat162float(h1));
                l[2 * j + 1].x = __float2bfloat16_rn(f2 - __bfloat162float(h2));
                l[2 * j + 1].y = __float2bfloat16_rn(f3 - __bfloat162float(h3));
            }
            *(uint4*)(tA + stoff0)  = *(uint4*)&h[0];
            *(uint4*)(tA + stoff1)  = *(uint4*)&h[4];
            *(uint4*)(tA + stoff0L) = *(uint4*)&l[0];
            *(uint4*)(tA + stoff1L) = *(uint4*)&l[4];
            *(float4*)(tB + stoff0)  = bhv[0];
            *(float4*)(tB + stoff1)  = bhv[1];
            *(float4*)(tB + stoff0L) = blv[0];
            *(float4*)(tB + stoff1L) = blv[1];
        }
        __syncthreads();

        if (c + 1 < NCH) {
            const int kc = (c + 1) * KCH;
            const float* ap = &A[(size_t)(bm + lrow) * DM + kc + lhalf * 16];
#pragma unroll
            for (int j = 0; j < 4; j++) av[j] = *(const float4*)(ap + 4 * j);
            const __nv_bfloat16* bhp = &BhiT[(size_t)(bn + lrow) * DM + kc + lhalf * 16];
            const __nv_bfloat16* blp = &BloT[(size_t)(bn + lrow) * DM + kc + lhalf * 16];
            bhv[0] = *(const float4*)bhp; bhv[1] = *(const float4*)(bhp + 8);
            blv[0] = *(const float4*)blp; blv[1] = *(const float4*)(blp + 8);
        }

        const uint32_t tAu = s0 + buf * 2 * OPTILE;
        const uint32_t tBu = tAu + OPTILE;
#pragma unroll
        for (int ks = 0; ks < 2; ks++) {
            uint32_t ah[2][4], al[2][4];
#pragma unroll
            for (int mb = 0; mb < 2; mb++) {
                uint32_t offH = sw128((a_m + mb * 16) * 128 + ks * 32 + a_kb);
                uint32_t offL = sw128((a_m + mb * 16) * 128 + 64 + ks * 32 + a_kb);
                ldsm_x4(ah[mb][0], ah[mb][1], ah[mb][2], ah[mb][3], tAu + offH);
                ldsm_x4(al[mb][0], al[mb][1], al[mb][2], al[mb][3], tAu + offL);
            }
#pragma unroll
            for (int p = 0; p < 4; p++) {
                uint32_t bh[4], bl[4];
                uint32_t offH = sw128((b_n + p * 16) * 128 + ks * 32 + b_kb);
                uint32_t offL = sw128((b_n + p * 16) * 128 + 64 + ks * 32 + b_kb);
                ldsm_x4(bh[0], bh[1], bh[2], bh[3], tBu + offH);
                ldsm_x4(bl[0], bl[1], bl[2], bl[3], tBu + offL);
#pragma unroll
                for (int mb = 0; mb < 2; mb++) {
#pragma unroll
                    for (int half = 0; half < 2; half++) {
                        float* d = acc[mb][p * 2 + half];
                        mma_bf16(d, ah[mb], &bh[half * 2]);
                        mma_bf16(d, ah[mb], &bl[half * 2]);
                        mma_bf16(d, al[mb], &bh[half * 2]);
                    }
                }
            }
        }
        __syncthreads();
    }

#pragma unroll
    for (int mb = 0; mb < 2; mb++) {
        int row0 = bm + wm * 32 + mb * 16 + (lane >> 2);
#pragma unroll
        for (int nb = 0; nb < 8; nb++) {
            int col = bn + wn * 64 + nb * 8 + (lane & 3) * 2;
            float2 b2 = *(const float2*)&bias[col];
            float2 v0 = make_float2(acc[mb][nb][0] + b2.x, acc[mb][nb][1] + b2.y);
            float2 v1 = make_float2(acc[mb][nb][2] + b2.x, acc[mb][nb][3] + b2.y);
            *(float2*)&C[(size_t)row0 * CORE + col] = v0;
            *(float2*)&C[(size_t)(row0 + 8) * CORE + col] = v1;
        }
    }
}

// split-K variant: A [M,Ktot] fp32, BT hi/lo [N,Ktot] bf16; block z handles
// K range [z*Kslice, (z+1)*Kslice); writes fp32 partial to Cpart[z][M][N].
__global__ __launch_bounds__(256) void gemm_sk_mma(
    const float* __restrict__ A,
    const __nv_bfloat16* __restrict__ BhiT, const __nv_bfloat16* __restrict__ BloT,
    float* __restrict__ Cpart, int Ktot, int Kslice, int N)
{
    extern __shared__ char smem[];
    const int tid = threadIdx.x;
    const int wid = tid >> 5, lane = tid & 31;
    const int wm = wid & 3, wn = wid >> 2;
    const int bm = blockIdx.y * 128;
    const int bn = blockIdx.x * 128;
    const int z  = blockIdx.z;
    const int k0 = z * Kslice;
    const int NCH = Kslice / KCH;

    uint32_t sbase = smem_u32(smem);
    uint32_t s0 = (sbase + 1023u) & ~1023u;
    char* smc = smem + (s0 - sbase);

    const int lrow  = tid >> 1;
    const int lhalf = tid & 1;
    const uint32_t stoff0  = sw128(lrow * 128 + lhalf * 32);
    const uint32_t stoff1  = sw128(lrow * 128 + lhalf * 32 + 16);
    const uint32_t stoff0L = sw128(lrow * 128 + 64 + lhalf * 32);
    const uint32_t stoff1L = sw128(lrow * 128 + 64 + lhalf * 32 + 16);

    const int g = lane >> 3, r = lane & 7;
    const int a_m  = wm * 32 + (g & 1) * 8 + r;
    const int a_kb = (g >> 1) * 16;
    const int b_n  = wn * 64 + ((g >> 1) & 1) * 8 + r;
    const int b_kb = (g & 1) * 16;

    float acc[2][8][4];
#pragma unroll
    for (int mb = 0; mb < 2; mb++)
#pragma unroll
        for (int nb = 0; nb < 8; nb++)
#pragma unroll
            for (int q = 0; q < 4; q++) acc[mb][nb][q] = 0.f;

    float4 av[4];
    float4 bhv[2], blv[2];
    {
        const float* ap = &A[(size_t)(bm + lrow) * Ktot + k0 + lhalf * 16];
#pragma unroll
        for (int j = 0; j < 4; j++) av[j] = *(const float4*)(ap + 4 * j);
        const __nv_bfloat16* bhp = &BhiT[(size_t)(bn + lrow) * Ktot + k0 + lhalf * 16];
        const __nv_bfloat16* blp = &BloT[(size_t)(bn + lrow) * Ktot + k0 + lhalf * 16];
        bhv[0] = *(const float4*)bhp; bhv[1] = *(const float4*)(bhp + 8);
        blv[0] = *(const float4*)blp; blv[1] = *(const float4*)(blp + 8);
    }

    for (int c = 0; c < NCH; c++) {
        const int buf = c & 1;
        char* tA = smc + buf * 2 * OPTILE;
        char* tB = tA + OPTILE;
        {
            __nv_bfloat162 h[8], l[8];
#pragma unroll
            for (int j = 0; j < 4; j++) {
                float f0 = av[j].x, f1 = av[j].y, f2 = av[j].z, f3 = av[j].w;
                __nv_bfloat16 h0 = __float2bfloat16_rn(f0), h1 = __float2bfloat16_rn(f1);
                __nv_bfloat16 h2 = __float2bfloat16_rn(f2), h3 = __float2bfloat16_rn(f3);
                h[2 * j].x = h0; h[2 * j].y = h1; h[2 * j + 1].x = h2; h[2 * j + 1].y = h3;
                l[2 * j].x = __float2bfloat16_rn(f0 - __bfloat162float(h0));
                l[2 * j].y = __float2bfloat16_rn(f1 - __bfloat162float(h1));
                l[2 * j + 1].x = __float2bfloat16_rn(f2 - __bfloat162float(h2));
                l[2 * j + 1].y = __float2bfloat16_rn(f3 - __bfloat162float(h3));
            }
            *(uint4*)(tA + stoff0)  = *(uint4*)&h[0];
            *(uint4*)(tA + stoff1)  = *(uint4*)&h[4];
            *(uint4*)(tA + stoff0L) = *(uint4*)&l[0];
            *(uint4*)(tA + stoff1L) = *(uint4*)&l[4];
            *(float4*)(tB + stoff0)  = bhv[0];
            *(float4*)(tB + stoff1)  = bhv[1];
            *(float4*)(tB + stoff0L) = blv[0];
            *(float4*)(tB + stoff1L) = blv[1];
        }
        __syncthreads();

        if (c + 1 < NCH) {
            const int kc = k0 + (c + 1) * KCH;
            const float* ap = &A[(size_t)(bm + lrow) * Ktot + kc + lhalf * 16];
#pragma unroll
            for (int j = 0; j < 4; j++) av[j] = *(const float4*)(ap + 4 * j);
            const __nv_bfloat16* bhp = &BhiT[(size_t)(bn + lrow) * Ktot + kc + lhalf * 16];
            const __nv_bfloat16* blp = &BloT[(size_t)(bn + lrow) * Ktot + kc + lhalf * 16];
            bhv[0] = *(const float4*)bhp; bhv[1] = *(const float4*)(bhp + 8);
            blv[0] = *(const float4*)blp; blv[1] = *(const float4*)(blp + 8);
        }

        const uint32_t tAu = s0 + buf * 2 * OPTILE;
        const uint32_t tBu = tAu + OPTILE;
#pragma unroll
        for (int ks = 0; ks < 2; ks++) {
            uint32_t ah[2][4], al[2][4];
#pragma unroll
            for (int mb = 0; mb < 2; mb++) {
                uint32_t offH = sw128((a_m + mb * 16) * 128 + ks * 32 + a_kb);
                uint32_t offL = sw128((a_m + mb * 16) * 128 + 64 + ks * 32 + a_kb);
                ldsm_x4(ah[mb][0], ah[mb][1], ah[mb][2], ah[mb][3], tAu + offH);
                ldsm_x4(al[mb][0], al[mb][1], al[mb][2], al[mb][3], tAu + offL);
            }
#pragma unroll
            for (int p = 0; p < 4; p++) {
                uint32_t bh[4], bl[4];
                uint32_t offH = sw128((b_n + p * 16) * 128 + ks * 32 + b_kb);
                uint32_t offL = sw128((b_n + p * 16) * 128 + 64 + ks * 32 + b_kb);
                ldsm_x4(bh[0], bh[1], bh[2], bh[3], tBu + offH);
                ldsm_x4(bl[0], bl[1], bl[2], bl[3], tBu + offL);
#pragma unroll
                for (int mb = 0; mb < 2; mb++) {
#pragma unroll
                    for (int half = 0; half < 2; half++) {
                        float* d = acc[mb][p * 2 + half];
                        mma_bf16(d, ah[mb], &bh[half * 2]);
                        mma_bf16(d, ah[mb], &bl[half * 2]);
                        mma_bf16(d, al[mb], &bh[half * 2]);
                    }
                }
            }
        }
        __syncthreads();
    }

    float* Cp = Cpart + (size_t)z * MSLOT * N;
#pragma unroll
    for (int mb = 0; mb < 2; mb++) {
        int row0 = bm + wm * 32 + mb * 16 + (lane >> 2);
#pragma unroll
        for (int nb = 0; nb < 8; nb++) {
            int col = bn + wn * 64 + nb * 8 + (lane & 3) * 2;
            *(float2*)&Cp[(size_t)row0 * N + col] = make_float2(acc[mb][nb][0], acc[mb][nb][1]);
            *(float2*)&Cp[(size_t)(row0 + 8) * N + col] = make_float2(acc[mb][nb][2], acc[mb][nb][3]);
        }
    }
}

// reduce split-K partials: C = (relu?)(sum_z Cpart[z] + bias)
template <bool RELU>
__global__ void reduce_sk(const float* __restrict__ Cpart, const float* __restrict__ bias,
                          float* __restrict__ C, int MN, int N, int SK)
{
    int i = blockIdx.x * 256 + threadIdx.x;
    if (i >= MN) return;
    float s = bias[i % N];
    for (int z = 0; z < SK; z++) s += Cpart[(size_t)z * MN + i];
    if (RELU) s = fmaxf(s, 0.f);
    C[i] = s;
}

// ---------------- scores + top-k + counts ----------------
#define TCHUNK 64
__global__ __launch_bounds__(256) void scores_topk(
    const float* __restrict__ kv, const float* __restrict__ qslots,
    const float* __restrict__ mbias,
    float* __restrict__ out_scores, float* __restrict__ out_gate,
    unsigned int* __restrict__ idx_out, int* __restrict__ counts)
{
    extern __shared__ float smemf[];
    float* q_s  = smemf;
    float* k_s  = q_s + 256 * 33;
    float* sc_s = k_s + 64 * 33;
    int*   hist = (int*)(sc_s + 256 * 65);

    const int h  = blockIdx.y;
    const int n0 = blockIdx.x * TCHUNK;
    const int tid = threadIdx.x;

    hist[tid] = 0;

    const int tm = tid >> 2;
    const int tt = tid & 3;

    float acc[4][16];
#pragma unroll
    for (int i = 0; i < 4; i++)
#pragma unroll
        for (int j = 0; j < 16; j++) acc[i][j] = 0.f;

    for (int dc = 0; dc < HD; dc += 32) {
        {
            const float* src = &qslots[(size_t)tid * CORE + h * HD + dc];
#pragma unroll
            for (int j = 0; j < 32; j += 4) {
                float4 v = *(const float4*)&src[j];
                q_s[tid * 33 + j + 0] = v.x; q_s[tid * 33 + j + 1] = v.y;
                q_s[tid * 33 + j + 2] = v.z; q_s[tid * 33 + j + 3] = v.w;
            }
        }
        {
            int t = tid >> 2; int cc = (tid & 3) * 8;
            const float* src = &kv[(size_t)(n0 + t) * CORE + h * HD + dc + cc];
            float4 v0 = *(const float4*)src;
            float4 v1 = *(const float4*)(src + 4);
            k_s[t * 33 + cc + 0] = v0.x; k_s[t * 33 + cc + 1] = v0.y;
            k_s[t * 33 + cc + 2] = v0.z; k_s[t * 33 + cc + 3] = v0.w;
            k_s[t * 33 + cc + 4] = v1.x; k_s[t * 33 + cc + 5] = v1.y;
            k_s[t * 33 + cc + 6] = v1.z; k_s[t * 33 + cc + 7] = v1.w;
        }
        __syncthreads();
#pragma unroll 8
        for (int dd = 0; dd < 32; dd++) {
            float a[4], b[16];
#pragma unroll
            for (int i = 0; i < 4; i++) a[i] = q_s[(tm * 4 + i) * 33 + dd];
#pragma unroll
            for (int j = 0; j < 16; j++) b[j] = k_s[(tt * 16 + j) * 33 + dd];
#pragma unroll
            for (int i = 0; i < 4; i++)
#pragma unroll
                for (int j = 0; j < 16; j++) acc[i][j] += a[i] * b[j];
        }
        __syncthreads();
    }

    const float scale = 0.08838834764831845f;
#pragma unroll
    for (int i = 0; i < 4; i++) {
        int m = tm * 4 + i;
        float bia = mbias[h * MSLOT + m] * 5.0f;
#pragma unroll
        for (int j = 0; j < 16; j++)
            sc_s[m * 65 + tt * 16 + j] = acc[i][j] * scale + bia;
    }
    __syncthreads();

    size_t base = ((size_t)h * MSLOT) * NTOK + n0;
    {
        int t = tid & 63;
        int mo = tid >> 6;
        for (int rr = 0; rr < 64; rr++) {
            int m = rr * 4 + mo;
            float v = sc_s[m * 65 + t];
            out_scores[base + (size_t)m * NTOK + t] = v;
            out_gate  [base + (size_t)m * NTOK + t] = v;
        }
    }
    __syncthreads();

    const int warp = tid >> 5, lane = tid & 31;
    for (int t = warp; t < TCHUNK; t += 8) {
        unsigned sel_pack = 0;
#pragma unroll
        for (int rr = 0; rr < TOPK; rr++) {
            float bv = -3.402823466e38f; int bi = 0;
#pragma unroll
            for (int j = 0; j < 8; j++) {
                int m = lane + j * 32;
                float v = sc_s[m * 65 + t];
                if (v > bv) { bv = v; bi = m; }
            }
#pragma unroll
            for (int off = 16; off; off >>= 1) {
                float ov = __shfl_xor_sync(0xffffffffu, bv, off);
                int   oi = __shfl_xor_sync(0xffffffffu, bi, off);
                if (ov > bv || (ov == bv && oi < bi)) { bv = ov; bi = oi; }
            }
            if (lane == 0) sc_s[bi * 65 + t] = -3.402823466e38f;
            __syncwarp();
            sel_pack |= ((unsigned)bi) << (8 * rr);
        }
        if (lane == 0) {
            idx_out[h * NTOK + n0 + t] = sel_pack;
            atomicAdd(&hist[sel_pack & 255], 1);
            atomicAdd(&hist[(sel_pack >> 8) & 255], 1);
            atomicAdd(&hist[(sel_pack >> 16) & 255], 1);
            atomicAdd(&hist[(sel_pack >> 24) & 255], 1);
        }
    }
    __syncthreads();
    if (hist[tid]) atomicAdd(&counts[h * MSLOT + tid], hist[tid]);
}

// ---------------- attended accumulation ----------------
__global__ __launch_bounds__(256) void attend_accum(
    const float* __restrict__ kv, const unsigned int* __restrict__ idx,
    float* __restrict__ att)
{
    extern __shared__ float a_s[];
    const int h  = blockIdx.y;
    const int n0 = blockIdx.x * 1024;
    const int tid = threadIdx.x;
    for (int i = tid; i < MSLOT * HD; i += 256) a_s[i] = 0.f;
    __syncthreads();

    const int warp = tid >> 5, lane = tid & 31;
    const int mlo = warp * 32, mhi = mlo + 32;

    for (int t = 0; t < 1024; t++) {
        unsigned p = idx[h * NTOK + n0 + t];
        const float4* krow = (const float4*)&kv[(size_t)(n0 + t) * CORE + h * HD];
#pragma unroll
        for (int r = 0; r < TOPK; r++) {
            int m = (p >> (8 * r)) & 255;
            if (m >= mlo && m < mhi) {
                float4 kval = krow[lane];
                float4* dst = (float4*)&a_s[m * HD + lane * 4];
                float4 d = *dst;
                d.x += kval.x; d.y += kval.y; d.z += kval.z; d.w += kval.w;
                *dst = d;
            }
        }
    }
    __syncthreads();
    for (int i = tid; i < MSLOT * HD; i += 256) {
        float v = a_s[i];
        if (v != 0.f) atomicAdd(&att[(size_t)h * MSLOT * HD + i], v);
    }
}

// ---------------- build upd_in = concat(mem, context) ----------------
__global__ void build_updin(const float* __restrict__ mem,
                            const float* __restrict__ att,
                            float* __restrict__ out)
{
    int row = blockIdx.x, tid = threadIdx.x;
    for (int i = tid; i < 2 * CORE; i += 256) {
        float v;
        if (i < CORE) v = mem[(size_t)row * CORE + i];
        else {
            int c = i - CORE; int h = c >> 7, d = c & 127;
            v = att[(h << 15) + row * HD + d];
        }
        out[(size_t)row * 2 * CORE + i] = v;
    }
}

// ---------------- layernorm ----------------
__global__ void ln_kernel(const float* __restrict__ x, const float* __restrict__ g,
                          const float* __restrict__ b, float* __restrict__ y, int L)
{
    int row = blockIdx.x, tid = threadIdx.x;
    const float* xr = &x[(size_t)row * L];
    float s = 0.f, s2 = 0.f;
    for (int i = tid; i < L; i += 256) { float v = xr[i]; s += v; s2 += v * v; }
    __shared__ float rs[8], rs2[8];
#pragma unroll
    for (int o = 16; o; o >>= 1) {
        s  += __shfl_xor_sync(0xffffffffu, s, o);
        s2 += __shfl_xor_sync(0xffffffffu, s2, o);
    }
    if ((tid & 31) == 0) { rs[tid >> 5] = s; rs2[tid >> 5] = s2; }
    __syncthreads();
    if (tid < 32) {
        s  = (tid < 8) ? rs[tid]  : 0.f;
        s2 = (tid < 8) ? rs2[tid] : 0.f;
#pragma unroll
        for (int o = 4; o; o >>= 1) {
            s  += __shfl_xor_sync(0xffffffffu, s, o);
            s2 += __shfl_xor_sync(0xffffffffu, s2, o);
        }
        if (tid == 0) { rs[0] = s; rs2[0] = s2; }
    }
    __syncthreads();
    float mu = rs[0] / (float)L;
    float var = rs2[0] / (float)L - mu * mu;
    float r = rsqrtf(var + 1e-5f);
    for (int i = tid; i < L; i += 256)
        y[(size_t)row * L + i] = (xr[i] - mu) * r * g[i] + b[i];
}

// ---------------- load fraction ----------------
__global__ void lf_kernel(const int* __restrict__ counts, float* __restrict__ out)
{
    int m = threadIdx.x;
    int s = 0;
#pragma unroll
    for (int h = 0; h < NH; h++) s += counts[h * MSLOT + m];
    out[m] = (float)s * 0.125f;
}

// ---------------- host launcher ----------------
extern "C" void kernel_launch(void* const* d_in, const int* in_sizes, int n_in,
                              void* d_out, int out_size)
{
    const float* bq_in   = (const float*)d_in[0];
    const float* mem     = (const float*)d_in[1];
    const float* Wq      = (const float*)d_in[2];
    const float* bq      = (const float*)d_in[3];
    const float* Ws1     = (const float*)d_in[4];
    const float* bs1     = (const float*)d_in[5];
    const float* Ws2     = (const float*)d_in[6];
    const float* bs2     = (const float*)d_in[7];
    const float* mbias   = (const float*)d_in[8];
    const float* ln1_g   = (const float*)d_in[9];
    const float* ln1_b   = (const float*)d_in[10];
    const float* Wu1     = (const float*)d_in[11];
    const float* bu1     = (const float*)d_in[12];
    const float* Wu2     = (const float*)d_in[13];
    const float* bu2     = (const float*)d_in[14];
    const float* lno_g   = (const float*)d_in[15];
    const float* lno_b   = (const float*)d_in[16];

    float* out = (float*)d_out;
    float* out_dyn    = out;
    float* out_scores = out + (size_t)MSLOT * CORE;
    float* out_gate   = out_scores + (size_t)NH * MSLOT * NTOK;
    float* out_lf     = out_gate + (size_t)NH * MSLOT * NTOK;

    void *p;
    cudaGetSymbolAddress(&p, g_kv);      float* kv  = (float*)p;
    cudaGetSymbolAddress(&p, g_hid);     float* hid = (float*)p;
    cudaGetSymbolAddress(&p, g_qslots);  float* qs  = (float*)p;
    cudaGetSymbolAddress(&p, g_att);     float* att = (float*)p;
    cudaGetSymbolAddress(&p, g_idx);     unsigned int* idxb = (unsigned int*)p;
    cudaGetSymbolAddress(&p, g_counts);  int* cnt = (int*)p;
    cudaGetSymbolAddress(&p, g_updin);   float* ui = (float*)p;
    cudaGetSymbolAddress(&p, g_h1);      float* h1 = (float*)p;
    cudaGetSymbolAddress(&p, g_hu);      float* hu = (float*)p;
    cudaGetSymbolAddress(&p, g_h2);      float* h2 = (float*)p;
    cudaGetSymbolAddress(&p, g_part);    float* part = (float*)p;
    cudaGetSymbolAddress(&p, g_BhiT);    __nv_bfloat16* BhiT = (__nv_bfloat16*)p;
    cudaGetSymbolAddress(&p, g_BloT);    __nv_bfloat16* BloT = (__nv_bfloat16*)p;
    cudaGetSymbolAddress(&p, g_W1h);     __nv_bfloat16* W1h = (__nv_bfloat16*)p;
    cudaGetSymbolAddress(&p, g_W1l);     __nv_bfloat16* W1l = (__nv_bfloat16*)p;
    cudaGetSymbolAddress(&p, g_W2h);     __nv_bfloat16* W2h = (__nv_bfloat16*)p;
    cudaGetSymbolAddress(&p, g_W2l);     __nv_bfloat16* W2l = (__nv_bfloat16*)p;
    cudaGetSymbolAddress(&p, g_U1h);     __nv_bfloat16* U1h = (__nv_bfloat16*)p;
    cudaGetSymbolAddress(&p, g_U1l);     __nv_bfloat16* U1l = (__nv_bfloat16*)p;
    cudaGetSymbolAddress(&p, g_U2h);     __nv_bfloat16* U2h = (__nv_bfloat16*)p;
    cudaGetSymbolAddress(&p, g_U2l);     __nv_bfloat16* U2l = (__nv_bfloat16*)p;

    int sm2 = (256 * 33 + 64 * 33 + 256 * 65 + 256) * 4;
    cudaFuncSetAttribute(scores_topk, cudaFuncAttributeMaxDynamicSharedMemorySize, sm2);
    int sm3 = MSLOT * HD * 4;
    cudaFuncSetAttribute(attend_accum, cudaFuncAttributeMaxDynamicSharedMemorySize, sm3);
    int smg = 4 * OPTILE + 1024;
    cudaFuncSetAttribute(kv_gemm_mma, cudaFuncAttributeMaxDynamicSharedMemorySize, smg);
    cudaFuncSetAttribute(gemm_sk_mma, cudaFuncAttributeMaxDynamicSharedMemorySize, smg);

    cudaMemsetAsync(cnt, 0, NH * MSLOT * sizeof(int));
    cudaMemsetAsync(att, 0, NH * MSLOT * HD * sizeof(float));

    // 0) weight transposes + bf16 hi/lo splits
    transB_gen<<<dim3(CORE / 32, DM / 32), dim3(32, 8)>>>(Wq, BhiT, BloT, DM, CORE);
    transB_gen<<<dim3(INTER / 32, CORE / 32), dim3(32, 8)>>>(Ws1, W1h, W1l, CORE, INTER);
    transB_gen<<<dim3(CORE / 32, INTER / 32), dim3(32, 8)>>>(Ws2, W2h, W2l, INTER, CORE);
    transB_gen<<<dim3(2 * CORE / 32, 2 * CORE / 32), dim3(32, 8)>>>(Wu1, U1h, U1l, 2 * CORE, 2 * CORE);
    transB_gen<<<dim3(CORE / 32, 2 * CORE / 32), dim3(32, 8)>>>(Wu2, U2h, U2l, 2 * CORE, CORE);

    // 1) kv = flat @ Wq + bq (HMMA split-precision)
    kv_gemm_mma<<<dim3(CORE / 128, NTOK / 128), 256, smg>>>(bq_in, BhiT, BloT, bq, kv);

    // 2) q_slots MLP (split-K HMMA)
    gemm_sk_mma<<<dim3(INTER / 128, 2, 4), 256, smg>>>(mem, W1h, W1l, part, CORE, 256, INTER);
    reduce_sk<true><<<(MSLOT * INTER + 255) / 256, 256>>>(part, bs1, hid, MSLOT * INTER, INTER, 4);
    gemm_sk_mma<<<dim3(CORE / 128, 2, 16), 256, smg>>>(hid, W2h, W2l, part, INTER, 256, CORE);
    reduce_sk<false><<<(MSLOT * CORE + 255) / 256, 256>>>(part, bs2, qs, MSLOT * CORE, CORE, 16);

    // 3) scores + topk + counts
    scores_topk<<<dim3(NTOK / TCHUNK, NH), 256, sm2>>>(kv, qs, mbias, out_scores, out_gate, idxb, cnt);

    // 4) attended
    attend_accum<<<dim3(NTOK / 1024, NH), 256, sm3>>>(kv, idxb, att);

    // 5) update MLP (split-K HMMA)
    build_updin<<<MSLOT, 256>>>(mem, att, ui);
    ln_kernel<<<MSLOT, 256>>>(ui, ln1_g, ln1_b, h1, 2 * CORE);
    gemm_sk_mma<<<dim3(2 * CORE / 128, 2, 8), 256, smg>>>(h1, U1h, U1l, part, 2 * CORE, 256, 2 * CORE);
    reduce_sk<true><<<(MSLOT * 2 * CORE + 255) / 256, 256>>>(part, bu1, hu, MSLOT * 2 * CORE, 2 * CORE, 8);
    gemm_sk_mma<<<dim3(CORE / 128, 2, 8), 256, smg>>>(hu, U2h, U2l, part, 2 * CORE, 256, CORE);
    reduce_sk<false><<<(MSLOT * CORE + 255) / 256, 256>>>(part, bu2, h2, MSLOT * CORE, CORE, 8);
    ln_kernel<<<MSLOT, 256>>>(h2, lno_g, lno_b, out_dyn, CORE);

    // 6) load fraction
    lf_kernel<<<1, MSLOT>>>(cnt, out_lf);
}